// round 15
// baseline (speedup 1.0000x reference)
#include <cuda_runtime.h>
#include <cuda_fp16.h>
#include <cstdint>

// ---------------------------------------------------------------------------
// Device scratch (allocation-free)
// ---------------------------------------------------------------------------
__device__ __align__(256) float g_vp[2 * 256 * 1024];  // partial v (+bias in z=0)
__device__ __align__(256) float g_sp[256 * 64];        // partial dots [row][slot]

// ---------------------------------------------------------------------------
// Helpers
// ---------------------------------------------------------------------------
__device__ __forceinline__ uint32_t smem_u32(const void* p) {
    uint32_t a;
    asm("{ .reg .u64 t; cvta.to.shared.u64 t, %1; cvt.u32.u64 %0, t; }"
        : "=r"(a) : "l"(p));
    return a;
}

__device__ __forceinline__ void ldsm_x4(uint32_t* r, uint32_t addr) {
    asm volatile("ldmatrix.sync.aligned.m8n8.x4.shared.b16 {%0,%1,%2,%3}, [%4];"
                 : "=r"(r[0]), "=r"(r[1]), "=r"(r[2]), "=r"(r[3])
                 : "r"(addr));
}

__device__ __forceinline__ void sts128(uint32_t addr, uint4 v) {
    asm volatile("st.shared.v4.b32 [%0], {%1,%2,%3,%4};"
                 :: "r"(addr), "r"(v.x), "r"(v.y), "r"(v.z), "r"(v.w) : "memory");
}

__device__ __forceinline__ void mma16816(float* d, const uint32_t* a,
                                         uint32_t b0, uint32_t b1) {
    asm volatile(
        "mma.sync.aligned.m16n8k16.row.col.f32.f16.f16.f32 "
        "{%0,%1,%2,%3}, {%4,%5,%6,%7}, {%8,%9}, {%0,%1,%2,%3};"
        : "+f"(d[0]), "+f"(d[1]), "+f"(d[2]), "+f"(d[3])
        : "r"(a[0]), "r"(a[1]), "r"(a[2]), "r"(a[3]), "r"(b0), "r"(b1));
}

__device__ __forceinline__ uint4 pack_hi8(const float4 a0, const float4 a1) {
    __half2 h0 = __floats2half2_rn(a0.x, a0.y);
    __half2 h1 = __floats2half2_rn(a0.z, a0.w);
    __half2 h2 = __floats2half2_rn(a1.x, a1.y);
    __half2 h3 = __floats2half2_rn(a1.z, a1.w);
    uint4 u;
    u.x = *reinterpret_cast<uint32_t*>(&h0);
    u.y = *reinterpret_cast<uint32_t*>(&h1);
    u.z = *reinterpret_cast<uint32_t*>(&h2);
    u.w = *reinterpret_cast<uint32_t*>(&h3);
    return u;
}

// ---------------------------------------------------------------------------
// GEMM: tile 32(M) x 64(N), grid (32, 8, 2) = 512 CTAs, occ 4 (~3.5 CTAs/SM
// -> ~3.5 warps/SMSP for latency hiding). Split-K 2 (8 chunks of 64 k).
// Raw fp32 staging regs; pack to fp16 at STS; single __syncthreads per chunk.
// bx < 16: k half (fused q-dot -> g_sp). bx >= 16: v half -> g_vp partials.
// ---------------------------------------------------------------------------
#define A_STAGE_B 4096
#define B_STAGE_B 8192

__global__ void __launch_bounds__(128, 4)
gemm_kernel(const float* __restrict__ x32, const float* __restrict__ q,
            const float* __restrict__ bias, const float* __restrict__ W32) {
    __shared__ __align__(1024) char smemA[2 * A_STAGE_B];
    __shared__ __align__(1024) char smemB[2 * B_STAGE_B];
    const uint32_t sbA = smem_u32(smemA);
    const uint32_t sbB = smem_u32(smemB);

    const int tid  = threadIdx.x;
    const int lane = tid & 31;
    const int wid  = tid >> 5;            // 0..3
    const int wy   = wid >> 1;            // warp m index (0/1): 16 rows each
    const int wx   = wid & 1;             // warp n index (0/1): 32 cols each
    const int gq   = lane >> 2;           // group id 0..7
    const int tq   = lane & 3;            // quad thread 0..3

    const int n0 = blockIdx.x * 64;       // 0..2047
    const int m0 = blockIdx.y * 32;       // 0..224
    const int z  = blockIdx.z;            // split-K half
    const int c0 = z * 8;

    // Raw fp32 staging: A 2 units (32 rows), B 4 units (64 rows) per thread.
    float4 areg[2][2], breg[4][2];
    auto ldg_AB = [&](int c) {
        const int koff = c * 64;
        #pragma unroll
        for (int s = 0; s < 2; s++) {
            int u = tid + 128 * s;
            int r = u >> 3, j = u & 7;
            const float4* sa = reinterpret_cast<const float4*>(
                x32 + (m0 + r) * 1024 + koff + j * 8);
            areg[s][0] = sa[0];
            areg[s][1] = sa[1];
        }
        #pragma unroll
        for (int s = 0; s < 4; s++) {
            int u = tid + 128 * s;
            int r = u >> 3, j = u & 7;
            const float4* sb = reinterpret_cast<const float4*>(
                W32 + (n0 + r) * 1024 + koff + j * 8);
            breg[s][0] = sb[0];
            breg[s][1] = sb[1];
        }
    };

    auto sts_AB = [&](int buf) {
        const uint32_t baseA = sbA + buf * A_STAGE_B;
        const uint32_t baseB = sbB + buf * B_STAGE_B;
        #pragma unroll
        for (int s = 0; s < 2; s++) {
            int u = tid + 128 * s;
            int r = u >> 3, j = u & 7;
            uint32_t swz = (uint32_t)((j ^ (r & 7)) << 4);
            sts128(baseA + r * 128 + swz, pack_hi8(areg[s][0], areg[s][1]));
        }
        #pragma unroll
        for (int s = 0; s < 4; s++) {
            int u = tid + 128 * s;
            int r = u >> 3, j = u & 7;
            uint32_t swz = (uint32_t)((j ^ (r & 7)) << 4);
            sts128(baseB + r * 128 + swz, pack_hi8(breg[s][0], breg[s][1]));
        }
    };

    float acc[4][4];
    #pragma unroll
    for (int nj = 0; nj < 4; nj++)
        #pragma unroll
        for (int e = 0; e < 4; e++)
            acc[nj][e] = 0.0f;

    // Prologue: chunk0 -> smem buf0; chunk1 -> regs; one sync.
    ldg_AB(c0 + 0);
    sts_AB(0);
    ldg_AB(c0 + 1);
    __syncthreads();

    const int lrow = lane & 15;
    const int lcb  = lane >> 4;

    for (int i = 0; i < 8; i++) {
        const int buf = i & 1;

        if (i + 1 < 8) sts_AB((i + 1) & 1);   // pack + store chunk i+1
        if (i + 2 < 8) ldg_AB(c0 + i + 2);    // raw prefetch chunk i+2

        const uint32_t sa = sbA + buf * A_STAGE_B;
        const uint32_t sB = sbB + buf * B_STAGE_B;

        #pragma unroll
        for (int ks = 0; ks < 4; ks++) {
            const int j = ks * 2 + lcb;
            uint32_t a[4], b[2][4];
            {
                int r = wy * 16 + lrow;
                ldsm_x4(a, sa + r * 128 + ((j ^ (r & 7)) << 4));
            }
            #pragma unroll
            for (int nb = 0; nb < 2; nb++) {
                int r = wx * 32 + nb * 16 + lrow;
                ldsm_x4(b[nb], sB + r * 128 + ((j ^ (r & 7)) << 4));
            }
            #pragma unroll
            for (int nj = 0; nj < 4; nj++) {
                const int nb = nj >> 1, sub = nj & 1;
                mma16816(acc[nj], a, b[nb][sub], b[nb][sub + 2]);
            }
        }
        __syncthreads();   // sts(i+1) visible; buffer swap safe
    }

    // ------------------------------------------------------------------
    // Fused epilogue. acc element (nj, e):
    //   row = m0 + wy*16 + gq + (e>=2 ? 8 : 0)
    //   col = n0 + wx*32 + nj*8 + 2*tq + (e&1)
    // Bias added only by the z==0 half.
    // ------------------------------------------------------------------
    float2 bb[4];
    #pragma unroll
    for (int nj = 0; nj < 4; nj++) {
        if (z == 0) {
            const int col = n0 + wx * 32 + nj * 8 + 2 * tq;
            bb[nj] = *reinterpret_cast<const float2*>(bias + col);
        } else {
            bb[nj].x = 0.0f; bb[nj].y = 0.0f;
        }
    }

    if (n0 < 1024) {
        // k half: partial dot with q -> g_sp[row][slot]
        float part[2];
        #pragma unroll
        for (int rh = 0; rh < 2; rh++) {
            const int row = m0 + wy * 16 + rh * 8 + gq;
            float s = 0.0f;
            #pragma unroll
            for (int nj = 0; nj < 4; nj++) {
                const int col = n0 + wx * 32 + nj * 8 + 2 * tq;
                float2 qq = *reinterpret_cast<const float2*>(q + row * 1024 + col);
                s += (acc[nj][rh * 2 + 0] + bb[nj].x) * qq.x;
                s += (acc[nj][rh * 2 + 1] + bb[nj].y) * qq.y;
            }
            part[rh] = s;
        }
        #pragma unroll
        for (int rh = 0; rh < 2; rh++) {
            part[rh] += __shfl_xor_sync(0xFFFFFFFFu, part[rh], 1);
            part[rh] += __shfl_xor_sync(0xFFFFFFFFu, part[rh], 2);
        }
        if (tq == 0) {
            const int slot = z * 32 + blockIdx.x * 2 + wx;   // 0..63
            #pragma unroll
            for (int rh = 0; rh < 2; rh++) {
                const int row = m0 + wy * 16 + rh * 8 + gq;
                g_sp[row * 64 + slot] = part[rh];
            }
        }
    } else {
        // v half: write partial v (+bias for z=0)
        float* vbase = g_vp + z * 256 * 1024;
        #pragma unroll
        for (int rh = 0; rh < 2; rh++) {
            const int row = m0 + wy * 16 + rh * 8 + gq;
            #pragma unroll
            for (int nj = 0; nj < 4; nj++) {
                const int col = (n0 - 1024) + wx * 32 + nj * 8 + 2 * tq;
                float2 o;
                o.x = acc[nj][rh * 2 + 0] + bb[nj].x;
                o.y = acc[nj][rh * 2 + 1] + bb[nj].y;
                *reinterpret_cast<float2*>(vbase + row * 1024 + col) = o;
            }
        }
    }
}

// ---------------------------------------------------------------------------
// Scale: out[b,:] = (v0[b,:]+v1[b,:]) * sum(g_sp[b][0..63])
// ---------------------------------------------------------------------------
__global__ __launch_bounds__(256) void scale_kernel(float* __restrict__ out) {
    const int b = blockIdx.x;
    const int t = threadIdx.x;
    const int w = t >> 5, l = t & 31;

    __shared__ float red[2];
    __shared__ float s_tot;
    float p = (t < 64) ? g_sp[b * 64 + t] : 0.0f;
    #pragma unroll
    for (int off = 16; off > 0; off >>= 1)
        p += __shfl_xor_sync(0xFFFFFFFFu, p, off);
    if (w < 2 && l == 0) red[w] = p;
    __syncthreads();
    if (t == 0) s_tot = red[0] + red[1];
    __syncthreads();
    const float s = s_tot;

    float4 v0 = reinterpret_cast<const float4*>(g_vp + b * 1024)[t];
    float4 v1 = reinterpret_cast<const float4*>(g_vp + 256 * 1024 + b * 1024)[t];
    float4 o;
    o.x = (v0.x + v1.x) * s;
    o.y = (v0.y + v1.y) * s;
    o.z = (v0.z + v1.z) * s;
    o.w = (v0.w + v1.w) * s;
    reinterpret_cast<float4*>(out + b * 1024)[t] = o;
}

// ---------------------------------------------------------------------------
extern "C" void kernel_launch(void* const* d_in, const int* in_sizes, int n_in,
                              void* d_out, int out_size) {
    const float* x  = (const float*)d_in[0];   // 256x1024
    const float* q  = (const float*)d_in[1];   // 256x1024
    const float* W  = (const float*)d_in[2];   // 2048x1024
    const float* bs = (const float*)d_in[3];   // 2048
    float* out = (float*)d_out;                // 256x1024

    gemm_kernel<<<dim3(32, 8, 2), 128>>>(x, q, bs, W);
    scale_kernel<<<256, 256>>>(out);
}

// round 17
// speedup vs baseline: 1.3961x; 1.3961x over previous
#include <cuda_runtime.h>
#include <cuda_fp16.h>
#include <cstdint>

// ---------------------------------------------------------------------------
// Device scratch (allocation-free)
// ---------------------------------------------------------------------------
__device__ __align__(256) float g_vp[4 * 256 * 1024];  // v partials, 4 z-slices
__device__ __align__(256) float g_sp[256 * 128];       // k-dot partials [row][slot]

// ---------------------------------------------------------------------------
// Helpers
// ---------------------------------------------------------------------------
__device__ __forceinline__ uint32_t smem_u32(const void* p) {
    uint32_t a;
    asm("{ .reg .u64 t; cvta.to.shared.u64 t, %1; cvt.u32.u64 %0, t; }"
        : "=r"(a) : "l"(p));
    return a;
}

__device__ __forceinline__ void ldsm_x4(uint32_t* r, uint32_t addr) {
    asm volatile("ldmatrix.sync.aligned.m8n8.x4.shared.b16 {%0,%1,%2,%3}, [%4];"
                 : "=r"(r[0]), "=r"(r[1]), "=r"(r[2]), "=r"(r[3])
                 : "r"(addr));
}

__device__ __forceinline__ void sts128(uint32_t addr, uint4 v) {
    asm volatile("st.shared.v4.b32 [%0], {%1,%2,%3,%4};"
                 :: "r"(addr), "r"(v.x), "r"(v.y), "r"(v.z), "r"(v.w) : "memory");
}

__device__ __forceinline__ void mma16816(float* d, const uint32_t* a,
                                         uint32_t b0, uint32_t b1) {
    asm volatile(
        "mma.sync.aligned.m16n8k16.row.col.f32.f16.f16.f32 "
        "{%0,%1,%2,%3}, {%4,%5,%6,%7}, {%8,%9}, {%0,%1,%2,%3};"
        : "+f"(d[0]), "+f"(d[1]), "+f"(d[2]), "+f"(d[3])
        : "r"(a[0]), "r"(a[1]), "r"(a[2]), "r"(a[3]), "r"(b0), "r"(b1));
}

__device__ __forceinline__ uint4 pack_hi8(const float4 a0, const float4 a1) {
    __half2 h0 = __floats2half2_rn(a0.x, a0.y);
    __half2 h1 = __floats2half2_rn(a0.z, a0.w);
    __half2 h2 = __floats2half2_rn(a1.x, a1.y);
    __half2 h3 = __floats2half2_rn(a1.z, a1.w);
    uint4 u;
    u.x = *reinterpret_cast<uint32_t*>(&h0);
    u.y = *reinterpret_cast<uint32_t*>(&h1);
    u.z = *reinterpret_cast<uint32_t*>(&h2);
    u.w = *reinterpret_cast<uint32_t*>(&h3);
    return u;
}

// ---------------------------------------------------------------------------
// GEMM: tile 128(M) x 128(N), 256 threads (8 warps 2x4, warp tile 64x32).
// Grid (16, 2, 4) = 128 CTAs, split-K 4 (4 chunks of 64 k per CTA).
// L2 traffic: W 8MB*2(y) + x 1MB*16(x) = 32 MB (half of the 64x64 config).
// Raw fp32 staging; pack fp16 at STS; single __syncthreads per chunk.
// bx < 8: k half -> q-dot partials (g_sp). bx >= 8: v half -> g_vp slices.
// ---------------------------------------------------------------------------
#define A_STAGE 16384
#define B_STAGE 16384
#define SMEM_TOTAL (2 * (A_STAGE + B_STAGE))   // 64 KB

__global__ void __launch_bounds__(256, 1)
gemm_kernel(const float* __restrict__ x32, const float* __restrict__ q,
            const float* __restrict__ bias, const float* __restrict__ W32) {
    extern __shared__ __align__(1024) char smem[];
    const uint32_t sbA = smem_u32(smem);
    const uint32_t sbB = sbA + 2 * A_STAGE;

    const int tid  = threadIdx.x;
    const int lane = tid & 31;
    const int wid  = tid >> 5;            // 0..7
    const int wy   = wid >> 2;            // 0/1 : 64 M-rows each
    const int wx   = wid & 3;             // 0..3: 32 N-cols each
    const int gq   = lane >> 2;           // 0..7
    const int tq   = lane & 3;            // 0..3

    const int n0 = blockIdx.x * 128;      // 0..1920 (kv col base)
    const int m0 = blockIdx.y * 128;      // 0 / 128
    const int z  = blockIdx.z;            // 0..3
    const int c0 = z * 4;                 // chunk base (chunks of 64 k)

    // Raw fp32 staging: 4 units (8k each) per operand per thread.
    float4 areg[4][2], breg[4][2];
    auto ldg_AB = [&](int c) {
        const int koff = c * 64;
        #pragma unroll
        for (int s = 0; s < 4; s++) {
            int u = tid + 256 * s;
            int r = u >> 3, j = u & 7;    // r 0..127, j 0..7
            const float4* sa = reinterpret_cast<const float4*>(
                x32 + (m0 + r) * 1024 + koff + j * 8);
            const float4* sb = reinterpret_cast<const float4*>(
                W32 + (n0 + r) * 1024 + koff + j * 8);
            areg[s][0] = sa[0];
            areg[s][1] = sa[1];
            breg[s][0] = sb[0];
            breg[s][1] = sb[1];
        }
    };

    auto sts_AB = [&](int buf) {
        const uint32_t baseA = sbA + buf * A_STAGE;
        const uint32_t baseB = sbB + buf * B_STAGE;
        #pragma unroll
        for (int s = 0; s < 4; s++) {
            int u = tid + 256 * s;
            int r = u >> 3, j = u & 7;
            uint32_t swz = (uint32_t)((j ^ (r & 7)) << 4);
            sts128(baseA + r * 128 + swz, pack_hi8(areg[s][0], areg[s][1]));
            sts128(baseB + r * 128 + swz, pack_hi8(breg[s][0], breg[s][1]));
        }
    };

    float acc[4][4][4];                   // [mi][nj][e]
    #pragma unroll
    for (int mi = 0; mi < 4; mi++)
        #pragma unroll
        for (int nj = 0; nj < 4; nj++)
            #pragma unroll
            for (int e = 0; e < 4; e++)
                acc[mi][nj][e] = 0.0f;

    // Prologue: chunk0 -> smem buf0; chunk1 -> regs; one sync.
    ldg_AB(c0 + 0);
    sts_AB(0);
    ldg_AB(c0 + 1);
    __syncthreads();

    const int lrow = lane & 15;
    const int lcb  = lane >> 4;

    for (int i = 0; i < 4; i++) {
        const int buf = i & 1;

        if (i + 1 < 4) sts_AB((i + 1) & 1);
        if (i + 2 < 4) ldg_AB(c0 + i + 2);

        const uint32_t sa = sbA + buf * A_STAGE;
        const uint32_t sB = sbB + buf * B_STAGE;

        #pragma unroll
        for (int ks = 0; ks < 4; ks++) {
            const int j = ks * 2 + lcb;
            uint32_t a[4][4], b[2][4];
            #pragma unroll
            for (int mi = 0; mi < 4; mi++) {
                int r = wy * 64 + mi * 16 + lrow;
                ldsm_x4(a[mi], sa + r * 128 + ((j ^ (r & 7)) << 4));
            }
            #pragma unroll
            for (int nb = 0; nb < 2; nb++) {
                int r = wx * 32 + nb * 16 + lrow;
                ldsm_x4(b[nb], sB + r * 128 + ((j ^ (r & 7)) << 4));
            }
            #pragma unroll
            for (int mi = 0; mi < 4; mi++)
                #pragma unroll
                for (int nj = 0; nj < 4; nj++) {
                    const int nb = nj >> 1, sub = nj & 1;
                    mma16816(acc[mi][nj], a[mi], b[nb][sub], b[nb][sub + 2]);
                }
        }
        __syncthreads();
    }

    // ------------------------------------------------------------------
    // Epilogue. acc element (mi, nj, e):
    //   row = m0 + wy*64 + mi*16 + rh*8 + gq   (rh = e>>1)
    //   col = n0 + wx*32 + nj*8 + 2*tq + (e&1)
    // Bias added only by the z==0 slice.
    // ------------------------------------------------------------------
    float2 bb[4];
    #pragma unroll
    for (int nj = 0; nj < 4; nj++) {
        if (z == 0) {
            const int col = n0 + wx * 32 + nj * 8 + 2 * tq;
            bb[nj] = *reinterpret_cast<const float2*>(bias + col);
        } else {
            bb[nj].x = 0.0f; bb[nj].y = 0.0f;
        }
    }

    if (blockIdx.x < 8) {
        // k half: per-row partial dot with q over this warp's 32 cols.
        float part[8];
        #pragma unroll
        for (int mi = 0; mi < 4; mi++)
            #pragma unroll
            for (int rh = 0; rh < 2; rh++) {
                const int row = m0 + wy * 64 + mi * 16 + rh * 8 + gq;
                float s = 0.0f;
                #pragma unroll
                for (int nj = 0; nj < 4; nj++) {
                    const int col = n0 + wx * 32 + nj * 8 + 2 * tq;
                    float2 qq = *reinterpret_cast<const float2*>(q + row * 1024 + col);
                    s += (acc[mi][nj][rh * 2 + 0] + bb[nj].x) * qq.x;
                    s += (acc[mi][nj][rh * 2 + 1] + bb[nj].y) * qq.y;
                }
                part[mi * 2 + rh] = s;
            }
        #pragma unroll
        for (int sl = 0; sl < 8; sl++) {
            part[sl] += __shfl_xor_sync(0xFFFFFFFFu, part[sl], 1);
            part[sl] += __shfl_xor_sync(0xFFFFFFFFu, part[sl], 2);
        }
        if (tq == 0) {
            const int slot = z * 32 + blockIdx.x * 4 + wx;   // 0..127
            #pragma unroll
            for (int sl = 0; sl < 8; sl++) {
                const int row = m0 + wy * 64 + (sl >> 1) * 16 + (sl & 1) * 8 + gq;
                g_sp[row * 128 + slot] = part[sl];
            }
        }
    } else {
        // v half: write partial v (+bias for z=0) into slice z.
        float* vbase = g_vp + z * 256 * 1024;
        const int vc0 = (blockIdx.x - 8) * 128;
        #pragma unroll
        for (int mi = 0; mi < 4; mi++)
            #pragma unroll
            for (int rh = 0; rh < 2; rh++) {
                const int row = m0 + wy * 64 + mi * 16 + rh * 8 + gq;
                #pragma unroll
                for (int nj = 0; nj < 4; nj++) {
                    const int col = vc0 + wx * 32 + nj * 8 + 2 * tq;
                    float2 o;
                    o.x = acc[mi][nj][rh * 2 + 0] + bb[nj].x;
                    o.y = acc[mi][nj][rh * 2 + 1] + bb[nj].y;
                    *reinterpret_cast<float2*>(vbase + row * 1024 + col) = o;
                }
            }
    }
}

// ---------------------------------------------------------------------------
// Scale: out[b,:] = (v0+v1+v2+v3)[b,:] * sum(g_sp[b][0..127])
// ---------------------------------------------------------------------------
__global__ __launch_bounds__(256) void scale_kernel(float* __restrict__ out) {
    const int b = blockIdx.x;
    const int t = threadIdx.x;
    const int w = t >> 5, l = t & 31;

    __shared__ float red[4];
    __shared__ float s_tot;
    float p = (t < 128) ? g_sp[b * 128 + t] : 0.0f;
    #pragma unroll
    for (int off = 16; off > 0; off >>= 1)
        p += __shfl_xor_sync(0xFFFFFFFFu, p, off);
    if (w < 4 && l == 0) red[w] = p;
    __syncthreads();
    if (t == 0) s_tot = (red[0] + red[1]) + (red[2] + red[3]);
    __syncthreads();
    const float s = s_tot;

    float4 v0 = reinterpret_cast<const float4*>(g_vp + 0 * 256 * 1024 + b * 1024)[t];
    float4 v1 = reinterpret_cast<const float4*>(g_vp + 1 * 256 * 1024 + b * 1024)[t];
    float4 v2 = reinterpret_cast<const float4*>(g_vp + 2 * 256 * 1024 + b * 1024)[t];
    float4 v3 = reinterpret_cast<const float4*>(g_vp + 3 * 256 * 1024 + b * 1024)[t];
    float4 o;
    o.x = ((v0.x + v1.x) + (v2.x + v3.x)) * s;
    o.y = ((v0.y + v1.y) + (v2.y + v3.y)) * s;
    o.z = ((v0.z + v1.z) + (v2.z + v3.z)) * s;
    o.w = ((v0.w + v1.w) + (v2.w + v3.w)) * s;
    reinterpret_cast<float4*>(out + b * 1024)[t] = o;
}

// ---------------------------------------------------------------------------
extern "C" void kernel_launch(void* const* d_in, const int* in_sizes, int n_in,
                              void* d_out, int out_size) {
    const float* x  = (const float*)d_in[0];   // 256x1024
    const float* q  = (const float*)d_in[1];   // 256x1024
    const float* W  = (const float*)d_in[2];   // 2048x1024
    const float* bs = (const float*)d_in[3];   // 2048
    float* out = (float*)d_out;                // 256x1024

    cudaFuncSetAttribute(gemm_kernel, cudaFuncAttributeMaxDynamicSharedMemorySize,
                         SMEM_TOTAL);
    gemm_kernel<<<dim3(16, 2, 4), 256, SMEM_TOTAL>>>(x, q, bs, W);
    scale_kernel<<<256, 256>>>(out);
}